// round 1
// baseline (speedup 1.0000x reference)
#include <cuda_runtime.h>
#include <cstdint>

// Problem constants (fixed by the dataset)
#define B_     2
#define NRES   2048
#define NATOM  16384
#define CS     384
#define COUT   50

// Scratch: per-residue logits [B, NRES, COUT] = 2*2048*50 floats = 3.2 MB
__device__ float g_res_logits[B_ * NRES * COUT];

// ---------------------------------------------------------------------------
// Kernel 1: res_logits[row][o] = dot(s[row,:], W[o,:]) + bias[o]
// rows = B_*NRES = 4096, K = 384, N = 50.
// Block: 64 (o) x 4 (rows) threads. K tiled by 64 through shared memory.
// W transposed into smem so the inner loop reads are broadcast (s) +
// conflict-free (Wt).
// ---------------------------------------------------------------------------
__global__ void __launch_bounds__(256)
res_logits_kernel(const float* __restrict__ s,
                  const float* __restrict__ W,
                  const float* __restrict__ bias)
{
    __shared__ float s_sm[4][64];
    __shared__ float wt_sm[64][65];   // [k][o], padded: odd stride -> no conflicts

    const int tx  = threadIdx.x;      // 0..63  -> output channel o
    const int ty  = threadIdx.y;      // 0..3   -> row within tile
    const int tid = ty * 64 + tx;     // 0..255
    const int row0 = blockIdx.x * 4;  // 1024 blocks cover 4096 rows

    float acc = 0.0f;

    for (int kt = 0; kt < CS; kt += 64) {
        // load s tile: 4 rows x 64 k, one element per thread, coalesced in k
        {
            const int r = tid >> 6;          // 0..3
            const int k = tid & 63;          // 0..63
            s_sm[r][k] = s[(size_t)(row0 + r) * CS + kt + k];
        }
        // load W tile transposed: W[o][kt+k] -> wt_sm[k][o]
        for (int idx = tid; idx < 64 * COUT; idx += 256) {
            const int o = idx >> 6;          // 0..49
            const int k = idx & 63;          // 0..63
            wt_sm[k][o] = W[(size_t)o * CS + kt + k];
        }
        __syncthreads();

        #pragma unroll
        for (int k = 0; k < 64; ++k) {
            // s_sm read is a broadcast (all lanes same address);
            // wt_sm read is stride-1 across lanes: conflict-free.
            acc = fmaf(s_sm[ty][k], wt_sm[k][tx], acc);
        }
        __syncthreads();
    }

    if (tx < COUT) {
        g_res_logits[(size_t)(row0 + ty) * COUT + tx] = acc + bias[tx];
    }
}

// ---------------------------------------------------------------------------
// Kernel 2: one warp per atom.
//   1) scan the one-hot row (2048 fp32 = 8 KB) with float4 loads,
//      early-exit via ballot once the '1' is found (expected ~53% of row read)
//   2) gather res_logits[b, idx, :] (50 floats) into out[b, atom, :]
// ---------------------------------------------------------------------------
__global__ void __launch_bounds__(256)
scan_gather_kernel(const float* __restrict__ tta,   // [B, NATOM, NRES]
                   float* __restrict__ out)         // [B, NATOM, COUT]
{
    const int gwarp = (blockIdx.x * blockDim.x + threadIdx.x) >> 5;
    const int lane  = threadIdx.x & 31;
    if (gwarp >= B_ * NATOM) return;

    // Row of the one-hot matrix for this atom (16B aligned: 8192B rows).
    const float4* __restrict__ row =
        reinterpret_cast<const float4*>(tta + (size_t)gwarp * NRES);

    int idx = 0;
    // 2048 floats = 512 float4. Warp covers 32 float4 (128 floats) per iter.
    #pragma unroll 1
    for (int it = 0; it < NRES / 128; ++it) {
        const int v4i = it * 32 + lane;
        const float4 v = row[v4i];
        int my = -1;
        const int jb = v4i << 2;
        if (v.x != 0.0f)      my = jb;
        else if (v.y != 0.0f) my = jb + 1;
        else if (v.z != 0.0f) my = jb + 2;
        else if (v.w != 0.0f) my = jb + 3;

        const unsigned m = __ballot_sync(0xffffffffu, my >= 0);
        if (m) {
            const int src = __ffs(m) - 1;
            idx = __shfl_sync(0xffffffffu, my, src);
            break;
        }
    }

    const int b = gwarp >> 14;   // gwarp / NATOM
    const float* __restrict__ src =
        g_res_logits + ((size_t)b * NRES + idx) * COUT;
    float* __restrict__ dst = out + (size_t)gwarp * COUT;

    // 50 floats per atom: two strided passes over the warp.
    #pragma unroll
    for (int o = lane; o < COUT; o += 32) {
        dst[o] = src[o];
    }
}

extern "C" void kernel_launch(void* const* d_in, const int* in_sizes, int n_in,
                              void* d_out, int out_size)
{
    const float* s    = (const float*)d_in[0];  // [B, NRES, CS]
    const float* tta  = (const float*)d_in[1];  // [B, NATOM, NRES] one-hot
    const float* W    = (const float*)d_in[2];  // [COUT, CS]
    const float* bias = (const float*)d_in[3];  // [COUT]
    float* out = (float*)d_out;                 // [B, NATOM, COUT]

    (void)in_sizes; (void)n_in; (void)out_size;

    // Kernel 1: 4096 rows / 4 rows-per-block = 1024 blocks
    dim3 blk1(64, 4, 1);
    res_logits_kernel<<<1024, blk1>>>(s, W, bias);

    // Kernel 2: one warp per atom -> 32768 warps, 8 warps/block -> 4096 blocks
    scan_gather_kernel<<<4096, 256>>>(tta, out);
}

// round 2
// speedup vs baseline: 1.6586x; 1.6586x over previous
#include <cuda_runtime.h>
#include <cstdint>

#define B_     2
#define NRES   2048
#define NATOM  16384
#define CS     384
#define COUT   50
#define OPAD   64          // padded out dim for tiling

// Scratch
__device__ float g_res_logits[B_ * NRES * COUT];   // [B*NRES, 50]
__device__ float g_Wt[CS * OPAD];                  // [k][o] transposed, zero-padded

// ---------------------------------------------------------------------------
// Kernel 0: transpose W [50,384] -> g_Wt [384,64] (pad o>=50 with 0)
// ---------------------------------------------------------------------------
__global__ void __launch_bounds__(256)
wt_transpose_kernel(const float* __restrict__ W)
{
    const int idx = blockIdx.x * blockDim.x + threadIdx.x;   // 0 .. 384*64-1
    if (idx >= CS * OPAD) return;
    const int k = idx >> 6;       // /64
    const int o = idx & 63;
    g_Wt[idx] = (o < COUT) ? W[(size_t)o * CS + k] : 0.0f;
}

// ---------------------------------------------------------------------------
// Kernel 1: res_logits = s @ Wt + b.  4096 rows x 50 outs, K=384.
// Block: 256 threads, tile 32 rows x 64 outs, K tiled by 128.
// Thread microtile: 2 rows x 4 outs (float4) -> 6 LDS per 32 FMA.
// Grid: 128 blocks (one wave on 148 SMs).
// ---------------------------------------------------------------------------
#define KT       128
#define RPB      32
#define K4       (KT/4)

__global__ void __launch_bounds__(256)
res_logits_kernel(const float* __restrict__ s,
                  const float* __restrict__ bias)
{
    __shared__ float s_sm[RPB][KT];      // 16 KB
    __shared__ float wt_sm[KT][OPAD];    // 32 KB  (total 48 KB)

    const int tid = threadIdx.x;
    const int to  = tid & 15;            // out group: o0 = 4*to
    const int tr  = tid >> 4;            // row group: rows 2*tr, 2*tr+1
    const int o0  = to << 2;
    const int r0  = tr << 1;
    const int r1  = r0 + 1;
    const int row0 = blockIdx.x * RPB;

    float4 accA = make_float4(0.f, 0.f, 0.f, 0.f);
    float4 accB = make_float4(0.f, 0.f, 0.f, 0.f);

    for (int kt = 0; kt < CS; kt += KT) {
        // --- load s tile: 32 rows x 128 k = 1024 float4, 4 per thread ---
        {
            const float4* __restrict__ sg = reinterpret_cast<const float4*>(s);
            float4* s4 = reinterpret_cast<float4*>(&s_sm[0][0]);
            #pragma unroll
            for (int i = 0; i < 4; ++i) {
                const int f = tid + 256 * i;          // 0..1023
                const int r = f >> 5;                 // /32 (32 f4 per row)
                const int c = f & 31;
                s4[f] = sg[(size_t)(row0 + r) * (CS / 4) + (kt >> 2) + c];
            }
        }
        // --- load wt tile: 128 k x 64 o = 2048 float4, 8 per thread ---
        {
            const float4* __restrict__ wg =
                reinterpret_cast<const float4*>(g_Wt + (size_t)kt * OPAD);
            float4* w4 = reinterpret_cast<float4*>(&wt_sm[0][0]);
            #pragma unroll
            for (int i = 0; i < 8; ++i) {
                const int f = tid + 256 * i;          // 0..2047
                w4[f] = wg[f];
            }
        }
        __syncthreads();

        // --- compute ---
        #pragma unroll 8
        for (int kk = 0; kk < KT; kk += 4) {
            const float4 sa = *reinterpret_cast<const float4*>(&s_sm[r0][kk]);
            const float4 sb = *reinterpret_cast<const float4*>(&s_sm[r1][kk]);
            const float4 w0 = *reinterpret_cast<const float4*>(&wt_sm[kk + 0][o0]);
            const float4 w1 = *reinterpret_cast<const float4*>(&wt_sm[kk + 1][o0]);
            const float4 w2 = *reinterpret_cast<const float4*>(&wt_sm[kk + 2][o0]);
            const float4 w3 = *reinterpret_cast<const float4*>(&wt_sm[kk + 3][o0]);

            accA.x = fmaf(sa.x, w0.x, accA.x); accA.y = fmaf(sa.x, w0.y, accA.y);
            accA.z = fmaf(sa.x, w0.z, accA.z); accA.w = fmaf(sa.x, w0.w, accA.w);
            accB.x = fmaf(sb.x, w0.x, accB.x); accB.y = fmaf(sb.x, w0.y, accB.y);
            accB.z = fmaf(sb.x, w0.z, accB.z); accB.w = fmaf(sb.x, w0.w, accB.w);

            accA.x = fmaf(sa.y, w1.x, accA.x); accA.y = fmaf(sa.y, w1.y, accA.y);
            accA.z = fmaf(sa.y, w1.z, accA.z); accA.w = fmaf(sa.y, w1.w, accA.w);
            accB.x = fmaf(sb.y, w1.x, accB.x); accB.y = fmaf(sb.y, w1.y, accB.y);
            accB.z = fmaf(sb.y, w1.z, accB.z); accB.w = fmaf(sb.y, w1.w, accB.w);

            accA.x = fmaf(sa.z, w2.x, accA.x); accA.y = fmaf(sa.z, w2.y, accA.y);
            accA.z = fmaf(sa.z, w2.z, accA.z); accA.w = fmaf(sa.z, w2.w, accA.w);
            accB.x = fmaf(sb.z, w2.x, accB.x); accB.y = fmaf(sb.z, w2.y, accB.y);
            accB.z = fmaf(sb.z, w2.z, accB.z); accB.w = fmaf(sb.z, w2.w, accB.w);

            accA.x = fmaf(sa.w, w3.x, accA.x); accA.y = fmaf(sa.w, w3.y, accA.y);
            accA.z = fmaf(sa.w, w3.z, accA.z); accA.w = fmaf(sa.w, w3.w, accA.w);
            accB.x = fmaf(sb.w, w3.x, accB.x); accB.y = fmaf(sb.w, w3.y, accB.y);
            accB.z = fmaf(sb.w, w3.z, accB.z); accB.w = fmaf(sb.w, w3.w, accB.w);
        }
        __syncthreads();
    }

    // --- epilogue: add bias, store (res_logits stride = 50) ---
    const float aA[4] = {accA.x, accA.y, accA.z, accA.w};
    const float aB[4] = {accB.x, accB.y, accB.z, accB.w};
    #pragma unroll
    for (int c = 0; c < 4; ++c) {
        const int o = o0 + c;
        if (o < COUT) {
            const float bv = bias[o];
            g_res_logits[(size_t)(row0 + r0) * COUT + o] = aA[c] + bv;
            g_res_logits[(size_t)(row0 + r1) * COUT + o] = aB[c] + bv;
        }
    }
}

// ---------------------------------------------------------------------------
// Kernel 2: one warp per atom. Scan one-hot row with 4 float4/lane per round
// (512 floats/round, MLP=4), ballot early-exit, then gather 50 floats.
// ---------------------------------------------------------------------------
__global__ void __launch_bounds__(256)
scan_gather_kernel(const float* __restrict__ tta,   // [B, NATOM, NRES]
                   float* __restrict__ out)         // [B, NATOM, COUT]
{
    const int gwarp = (blockIdx.x * blockDim.x + threadIdx.x) >> 5;
    const int lane  = threadIdx.x & 31;

    const float4* __restrict__ row =
        reinterpret_cast<const float4*>(tta + (size_t)gwarp * NRES);

    int idx = 0;
    // NRES = 2048 floats = 512 float4; rounds of 128 float4 (512 floats) -> 4 rounds
    #pragma unroll 1
    for (int r = 0; r < 4; ++r) {
        float4 v[4];
        #pragma unroll
        for (int j = 0; j < 4; ++j)
            v[j] = row[r * 128 + j * 32 + lane];      // 4 independent LDG.128

        int my = -1;
        #pragma unroll
        for (int j = 3; j >= 0; --j) {
            const int jb = (r * 128 + j * 32 + lane) << 2;
            if (v[j].w != 0.0f) my = jb + 3;
            if (v[j].z != 0.0f) my = jb + 2;
            if (v[j].y != 0.0f) my = jb + 1;
            if (v[j].x != 0.0f) my = jb;
        }

        const unsigned m = __ballot_sync(0xffffffffu, my >= 0);
        if (m) {
            const int srcl = __ffs(m) - 1;
            idx = __shfl_sync(0xffffffffu, my, srcl);
            break;
        }
    }

    const int b = gwarp >> 14;
    const float* __restrict__ src =
        g_res_logits + ((size_t)b * NRES + idx) * COUT;
    float* __restrict__ dst = out + (size_t)gwarp * COUT;

    #pragma unroll
    for (int o = lane; o < COUT; o += 32)
        dst[o] = src[o];
}

extern "C" void kernel_launch(void* const* d_in, const int* in_sizes, int n_in,
                              void* d_out, int out_size)
{
    const float* s    = (const float*)d_in[0];  // [B, NRES, CS]
    const float* tta  = (const float*)d_in[1];  // [B, NATOM, NRES]
    const float* W    = (const float*)d_in[2];  // [COUT, CS]
    const float* bias = (const float*)d_in[3];  // [COUT]
    float* out = (float*)d_out;

    (void)in_sizes; (void)n_in; (void)out_size;

    wt_transpose_kernel<<<(CS * OPAD + 255) / 256, 256>>>(W);
    res_logits_kernel<<<(B_ * NRES) / RPB, 256>>>(s, bias);   // 128 blocks
    scan_gather_kernel<<<(B_ * NATOM) / 8, 256>>>(tta, out);  // 4096 blocks
}

// round 3
// speedup vs baseline: 2.1602x; 1.3025x over previous
#include <cuda_runtime.h>
#include <cstdint>

#define B_     2
#define NRES   2048
#define NATOM  16384
#define CS     384
#define COUT   50
#define OPAD   64
#define KT     64
#define RPB    32
#define GEMM_BLOCKS ((B_ * NRES) / RPB)   // 128
#define SCAN_BLOCKS ((B_ * NATOM) / 8)    // 4096

// Scratch
__device__ float g_res_logits[B_ * NRES * COUT];   // 3.2 MB
__device__ int   g_idx[B_ * NATOM];                // 128 KB

// ---------------------------------------------------------------------------
// Fused kernel:
//   blocks [0, 128):      GEMM  res_logits = s @ W^T + b  (32 rows/block)
//                         with per-block in-smem transpose of W
//   blocks [128, 4224):   one-hot scan, warp per atom, early exit -> g_idx
// The two halves are independent; GEMM hides under the DRAM-bound scan.
// ---------------------------------------------------------------------------
__global__ void __launch_bounds__(256)
fused_kernel(const float* __restrict__ s,     // [B, NRES, CS]
             const float* __restrict__ tta,   // [B, NATOM, NRES]
             const float* __restrict__ W,     // [COUT, CS]
             const float* __restrict__ bias)  // [COUT]
{
    __shared__ float s_sm[RPB][KT];     // 8 KB
    __shared__ float wt_sm[KT][OPAD];   // 16 KB   (24 KB total)

    const int tid = threadIdx.x;

    if (blockIdx.x < GEMM_BLOCKS) {
        // ----------------- GEMM branch -----------------
        const int to  = tid & 15;         // o-group: o0 = 4*to
        const int tr  = tid >> 4;         // row-group: rows 2*tr, 2*tr+1
        const int o0  = to << 2;
        const int r0  = tr << 1;
        const int r1  = r0 + 1;
        const int row0 = blockIdx.x * RPB;

        // W-transpose mapping: warp-lane strides o -> conflict-free STS
        const int wo = tid & 63;          // output channel for W loads
        const int wg = tid >> 6;          // k-group 0..3 (16 k each)

        float4 accA = make_float4(0.f, 0.f, 0.f, 0.f);
        float4 accB = make_float4(0.f, 0.f, 0.f, 0.f);

        for (int kt = 0; kt < CS; kt += KT) {
            // load s tile: 32 rows x 64 k = 512 float4, 2 per thread (coalesced)
            {
                const float4* __restrict__ sg = reinterpret_cast<const float4*>(s);
                float4* s4 = reinterpret_cast<float4*>(&s_sm[0][0]);
                #pragma unroll
                for (int i = 0; i < 2; ++i) {
                    const int f = tid + 256 * i;      // 0..511
                    const int r = f >> 4;             // 16 f4 per row
                    const int c = f & 15;
                    s4[f] = sg[(size_t)(row0 + r) * (CS / 4) + (kt >> 2) + c];
                }
            }
            // transpose W tile: thread loads W[wo][kt + 16*wg + 4m .. +3] (float4,
            // L2-hot), stores scalar to wt_sm[k][wo]; lanes stride wo -> no conflicts
            #pragma unroll
            for (int m = 0; m < 4; ++m) {
                const int k0 = (wg << 4) + (m << 2);
                float4 v = make_float4(0.f, 0.f, 0.f, 0.f);
                if (wo < COUT)
                    v = *reinterpret_cast<const float4*>(&W[(size_t)wo * CS + kt + k0]);
                wt_sm[k0 + 0][wo] = v.x;
                wt_sm[k0 + 1][wo] = v.y;
                wt_sm[k0 + 2][wo] = v.z;
                wt_sm[k0 + 3][wo] = v.w;
            }
            __syncthreads();

            #pragma unroll
            for (int kk = 0; kk < KT; kk += 4) {
                const float4 sa = *reinterpret_cast<const float4*>(&s_sm[r0][kk]);
                const float4 sb = *reinterpret_cast<const float4*>(&s_sm[r1][kk]);
                const float4 w0 = *reinterpret_cast<const float4*>(&wt_sm[kk + 0][o0]);
                const float4 w1 = *reinterpret_cast<const float4*>(&wt_sm[kk + 1][o0]);
                const float4 w2 = *reinterpret_cast<const float4*>(&wt_sm[kk + 2][o0]);
                const float4 w3 = *reinterpret_cast<const float4*>(&wt_sm[kk + 3][o0]);

                accA.x = fmaf(sa.x, w0.x, accA.x); accA.y = fmaf(sa.x, w0.y, accA.y);
                accA.z = fmaf(sa.x, w0.z, accA.z); accA.w = fmaf(sa.x, w0.w, accA.w);
                accB.x = fmaf(sb.x, w0.x, accB.x); accB.y = fmaf(sb.x, w0.y, accB.y);
                accB.z = fmaf(sb.x, w0.z, accB.z); accB.w = fmaf(sb.x, w0.w, accB.w);

                accA.x = fmaf(sa.y, w1.x, accA.x); accA.y = fmaf(sa.y, w1.y, accA.y);
                accA.z = fmaf(sa.y, w1.z, accA.z); accA.w = fmaf(sa.y, w1.w, accA.w);
                accB.x = fmaf(sb.y, w1.x, accB.x); accB.y = fmaf(sb.y, w1.y, accB.y);
                accB.z = fmaf(sb.y, w1.z, accB.z); accB.w = fmaf(sb.y, w1.w, accB.w);

                accA.x = fmaf(sa.z, w2.x, accA.x); accA.y = fmaf(sa.z, w2.y, accA.y);
                accA.z = fmaf(sa.z, w2.z, accA.z); accA.w = fmaf(sa.z, w2.w, accA.w);
                accB.x = fmaf(sb.z, w2.x, accB.x); accB.y = fmaf(sb.z, w2.y, accB.y);
                accB.z = fmaf(sb.z, w2.z, accB.z); accB.w = fmaf(sb.z, w2.w, accB.w);

                accA.x = fmaf(sa.w, w3.x, accA.x); accA.y = fmaf(sa.w, w3.y, accA.y);
                accA.z = fmaf(sa.w, w3.z, accA.z); accA.w = fmaf(sa.w, w3.w, accA.w);
                accB.x = fmaf(sb.w, w3.x, accB.x); accB.y = fmaf(sb.w, w3.y, accB.y);
                accB.z = fmaf(sb.w, w3.z, accB.z); accB.w = fmaf(sb.w, w3.w, accB.w);
            }
            __syncthreads();
        }

        const float aA[4] = {accA.x, accA.y, accA.z, accA.w};
        const float aB[4] = {accB.x, accB.y, accB.z, accB.w};
        #pragma unroll
        for (int c = 0; c < 4; ++c) {
            const int o = o0 + c;
            if (o < COUT) {
                const float bv = bias[o];
                g_res_logits[(size_t)(row0 + r0) * COUT + o] = aA[c] + bv;
                g_res_logits[(size_t)(row0 + r1) * COUT + o] = aB[c] + bv;
            }
        }
    } else {
        // ----------------- scan branch: warp per atom -----------------
        const int gwarp = (blockIdx.x - GEMM_BLOCKS) * 8 + (tid >> 5);
        const int lane  = tid & 31;

        const float4* __restrict__ row =
            reinterpret_cast<const float4*>(tta + (size_t)gwarp * NRES);

        int idx = 0;
        // 512 float4 per row; rounds of 128 float4 (512 floats), 4 f4/lane MLP
        #pragma unroll 1
        for (int r = 0; r < 4; ++r) {
            float4 v[4];
            #pragma unroll
            for (int j = 0; j < 4; ++j)
                v[j] = __ldcs(&row[r * 128 + j * 32 + lane]);   // streaming loads

            int my = -1;
            #pragma unroll
            for (int j = 3; j >= 0; --j) {
                const int jb = (r * 128 + j * 32 + lane) << 2;
                if (v[j].w != 0.0f) my = jb + 3;
                if (v[j].z != 0.0f) my = jb + 2;
                if (v[j].y != 0.0f) my = jb + 1;
                if (v[j].x != 0.0f) my = jb;
            }

            const unsigned m = __ballot_sync(0xffffffffu, my >= 0);
            if (m) {
                idx = __shfl_sync(0xffffffffu, my, __ffs(m) - 1);
                break;
            }
        }

        if (lane == 0) g_idx[gwarp] = idx;
    }
}

// ---------------------------------------------------------------------------
// Gather: out[b, atom, :] = res_logits[b, g_idx[b*NATOM+atom], :]
// Warp per atom; 25 lanes x float2 = 200 B. src in L2, writes coalesced.
// ---------------------------------------------------------------------------
__global__ void __launch_bounds__(256)
gather_kernel(float* __restrict__ out)
{
    const int gwarp = (blockIdx.x * blockDim.x + threadIdx.x) >> 5;
    const int lane  = threadIdx.x & 31;

    const int idx = g_idx[gwarp];          // uniform per warp
    const int b   = gwarp >> 14;

    const float2* __restrict__ src = reinterpret_cast<const float2*>(
        g_res_logits + ((size_t)b * NRES + idx) * COUT);
    float2* __restrict__ dst = reinterpret_cast<float2*>(
        out + (size_t)gwarp * COUT);

    if (lane < COUT / 2) dst[lane] = src[lane];
}

extern "C" void kernel_launch(void* const* d_in, const int* in_sizes, int n_in,
                              void* d_out, int out_size)
{
    const float* s    = (const float*)d_in[0];  // [B, NRES, CS]
    const float* tta  = (const float*)d_in[1];  // [B, NATOM, NRES]
    const float* W    = (const float*)d_in[2];  // [COUT, CS]
    const float* bias = (const float*)d_in[3];  // [COUT]
    float* out = (float*)d_out;

    (void)in_sizes; (void)n_in; (void)out_size;

    fused_kernel<<<GEMM_BLOCKS + SCAN_BLOCKS, 256>>>(s, tta, W, bias);
    gather_kernel<<<(B_ * NATOM) / 8, 256>>>(out);
}